// round 16
// baseline (speedup 1.0000x reference)
#include <cuda_runtime.h>
#include <cuda_fp16.h>
#include <cstdint>

// Problem constants (fixed by dataset): B=262144, D=32, R=16
#define R 16

// Bit layout (bit i = X[b][i]):
//   bits 0..9   -> U table (1024 fp32): e_{x0}*F * M0..M8
//   bits 10..15 -> pair table P0 (64 fp16 mats): M9*...*M14
//   bits 16..21 -> pair table P1 (64 fp16 mats): M15*...*M20
//   bits 22..31 -> W table (1024 fp32): M21..M29 * last_{x31}
// Per batch: v = U[j0]; v = v @ P0[j1]; v = v @ P1[j2]; out = dot(v, W[j3])

__device__ float    g_U[1024 * 16];
__device__ __half   g_P[2 * 64 * 256];
__device__ float    g_W[1024 * 16];

// ---------------------------------------------------------------------------
// Packed f32x2 helpers (sm_103a FFMA2 — only reachable via PTX fma.rn.f32x2)
// ---------------------------------------------------------------------------
__device__ __forceinline__ unsigned long long pack2(float a, float b) {
    unsigned long long r;
    asm("mov.b64 %0, {%1, %2};" : "=l"(r) : "f"(a), "f"(b));
    return r;
}
__device__ __forceinline__ void unpack2(unsigned long long p, float& a, float& b) {
    asm("mov.b64 {%0, %1}, %2;" : "=f"(a), "=f"(b) : "l"(p));
}
__device__ __forceinline__ unsigned long long ffma2(unsigned long long a,
                                                    unsigned long long b,
                                                    unsigned long long c) {
    unsigned long long d;
    asm("fma.rn.f32x2 %0, %1, %2, %3;" : "=l"(d) : "l"(a), "l"(b), "l"(c));
    return d;
}
__device__ __forceinline__ unsigned long long fmul2(unsigned long long a,
                                                    unsigned long long b) {
    unsigned long long d;
    asm("mul.rn.f32x2 %0, %1, %2;" : "=l"(d) : "l"(a), "l"(b));
    return d;
}
__device__ __forceinline__ unsigned long long fadd2(unsigned long long a,
                                                    unsigned long long b) {
    unsigned long long d;
    asm("add.rn.f32x2 %0, %1, %2;" : "=l"(d) : "l"(a), "l"(b));
    return d;
}
// fp16 pair (u32) -> f32x2 (u64)
__device__ __forceinline__ unsigned long long h2f2(unsigned h) {
    unsigned long long d;
    asm("{\n\t.reg .b16 l, hh;\n\t.reg .f32 f0, f1;\n\t"
        "mov.b32 {l, hh}, %1;\n\t"
        "cvt.f32.f16 f0, l;\n\t"
        "cvt.f32.f16 f1, hh;\n\t"
        "mov.b64 %0, {f0, f1};\n\t}" : "=l"(d) : "r"(h));
    return d;
}

// ---------------------------------------------------------------------------
// Prep kernel: TABLE BUILDERS ONLY (256 blocks x 256 threads, all
// warp-collaborative; mask packing is fused into tt_main).
//   blocks [0, 64)    : U entries
//   blocks [64, 128)  : W entries
//   blocks [128, 256) : P pair-product columns (16 lanes/column)
// ---------------------------------------------------------------------------
__global__ void prep(const float* __restrict__ cf,
                     const float* __restrict__ cm,
                     const float* __restrict__ cl) {
    int bid  = blockIdx.x;
    int lane = threadIdx.x & 31;
    int half = lane >> 4;
    int l16  = lane & 15;
    if (bid < 64) {
        // U[j][s] = (e_{x0} F) * M_{0,b1} * ... * M_{8,b9}
        int gwarp = (bid * 256 + threadIdx.x) >> 5;   // 0..511
        int s = l16;
        int j = gwarp * 2 + half;                     // 0..1023
        float v = cf[s * 2 + (j & 1)];
        for (int i = 0; i < 9; i++) {
            int b = (j >> (i + 1)) & 1;
            float nv = 0.f;
            #pragma unroll
            for (int r = 0; r < 16; r++) {
                float vr = __shfl_sync(0xffffffffu, v, (half << 4) + r);
                nv += vr * cm[((i * 16 + r) * 16 + s) * 2 + b];
            }
            v = nv;
        }
        g_U[j * 16 + s] = v;
    } else if (bid < 128) {
        // W[j][r] = (M_{21,b0} * ... * M_{29,b8} * lastcol_{b9})[r]
        int gwarp = ((bid - 64) * 256 + threadIdx.x) >> 5;
        int r = l16;
        int j = gwarp * 2 + half;
        float v = cl[r * 2 + ((j >> 9) & 1)];
        for (int i = 8; i >= 0; i--) {
            int c = 21 + i;
            int b = (j >> i) & 1;
            float nv = 0.f;
            #pragma unroll
            for (int t = 0; t < 16; t++) {
                float vt = __shfl_sync(0xffffffffu, v, (half << 4) + t);
                nv += cm[((c * 16 + r) * 16 + t) * 2 + b] * vt;
            }
            v = nv;
        }
        g_W[j * 16 + r] = v;
    } else {
        // P[g][idx] = M_{9+6g,b0} * ... * M_{14+6g,b5}, fp16.
        // One 16-lane half-warp per output column (g, idx, s); lane = row r.
        int col = (bid - 128) * 16 + (threadIdx.x >> 4);   // 0..2047
        int g   = col >> 10;                               // 0..1
        int idx = (col >> 4) & 63;                         // 0..63
        int s   = col & 15;
        int r   = l16;
        int c5  = 9 + 6 * g + 5;
        int b5  = (idx >> 5) & 1;
        float v = cm[((c5 * 16 + r) * 16 + s) * 2 + b5];
        for (int jj = 4; jj >= 0; jj--) {
            int c = 9 + 6 * g + jj;
            int b = (idx >> jj) & 1;
            float nv = 0.f;
            #pragma unroll
            for (int t = 0; t < 16; t++) {
                float vt = __shfl_sync(0xffffffffu, v, (half << 4) + t);
                nv += cm[((c * 16 + r) * 16 + t) * 2 + b] * vt;
            }
            v = nv;
        }
        g_P[(g * 64 + idx) * 256 + r * 16 + s] = __float2half_rn(v);
    }
}

// ---------------------------------------------------------------------------
// Main kernel: 640 threads/block (empirically best), fused mask pack with
// SOFTWARE PIPELINING: the warp pulls its next group and issues those 8
// coalesced X loads BEFORE computing the current group, so the DRAM wait is
// hidden under ~500 cycles of FFMA2/LDS work. Dynamic per-block scheduling
// via smem atomic removes the warp-tail quantization.
// smem: sU[1024*20 f32], sW[1024*20 f32], sP[128 mats * 264 halves]
// (264-half stride = 33 x 16B units -> unit bank-group = (idx + u) mod 8).
// ---------------------------------------------------------------------------
#define UW_STRIDE 20
#define SUW_FLOATS (1024 * UW_STRIDE)
#define P_STRIDE_H 264
#define SP_HALFS (128 * P_STRIDE_H)
#define SMEM_BYTES (2 * SUW_FLOATS * 4 + SP_HALFS * 2)   // 231424

#define NTHR 640
#define NWARP (NTHR / 32)

extern __shared__ float sm_buf[];

// Build 32 row-masks from 8 coalesced int4 tiles via shfl-OR trees.
// iter h covers rows base+4h..base+4h+3; lane l holds cols (l&7)*4..+3
// of row base+4h+(l>>3). Returns lane i's mask = row base+i.
__device__ __forceinline__ unsigned ortree_masks(const int4* t, int lane) {
    unsigned m = 0;
    #pragma unroll
    for (int h = 0; h < 8; h++) {
        int4 x4 = t[h];
        unsigned nib = (unsigned)(x4.x | (x4.y << 1) | (x4.z << 2) | (x4.w << 3))
                       << ((lane & 7) * 4);
        nib |= __shfl_xor_sync(0xffffffffu, nib, 1);
        nib |= __shfl_xor_sync(0xffffffffu, nib, 2);
        nib |= __shfl_xor_sync(0xffffffffu, nib, 4);
        unsigned rowmask = __shfl_sync(0xffffffffu, nib, (lane & 3) << 3);
        if ((lane >> 2) == h) m = rowmask;
    }
    return m;
}

__global__ __launch_bounds__(NTHR, 1) void tt_main(const int* __restrict__ X,
                                                   float* __restrict__ out, int B) {
    __shared__ int s_ctr;
    float*  sU = sm_buf;
    float*  sW = sm_buf + SUW_FLOATS;
    __half* sP = (__half*)(sm_buf + 2 * SUW_FLOATS);

    if (threadIdx.x == 0) s_ctr = 0;
    for (int i = threadIdx.x; i < 1024 * 16; i += NTHR) {
        sU[(i >> 4) * UW_STRIDE + (i & 15)] = g_U[i];
        sW[(i >> 4) * UW_STRIDE + (i & 15)] = g_W[i];
    }
    {   // stage P as u32 pairs
        const unsigned* gp32 = (const unsigned*)g_P;
        for (int i = threadIdx.x; i < (2 * 64 * 256) / 2; i += NTHR) {
            int e = i << 1;                   // even half index
            unsigned* dst = (unsigned*)(sP + (e >> 8) * P_STRIDE_H + (e & 255));
            *dst = gp32[i];
        }
    }
    __syncthreads();

    int lane = threadIdx.x & 31;
    int groups = B >> 5;                       // 8192 groups of 32 batches
    // Contiguous per-block slice (block-level imbalance ~2%).
    int start = (int)((long long)blockIdx.x * groups / gridDim.x);
    int end   = (int)((long long)(blockIdx.x + 1) * groups / gridDim.x);

    // ---- pipeline prologue: pull first group, load + build its masks ----
    int my;
    if (lane == 0) my = atomicAdd(&s_ctr, 1);
    my = __shfl_sync(0xffffffffu, my, 0);
    int g = start + my;
    unsigned mask = 0;
    if (g < end) {
        int4 t[8];
        const int4* xp = (const int4*)(X + (long long)(g << 5) * 32);
        #pragma unroll
        for (int h = 0; h < 8; h++) t[h] = xp[h * 32 + lane];
        mask = ortree_masks(t, lane);
    }

    while (g < end) {
        // ---- pull next group and ISSUE its X loads now (hidden by compute) ----
        int my2;
        if (lane == 0) my2 = atomicAdd(&s_ctr, 1);
        my2 = __shfl_sync(0xffffffffu, my2, 0);
        int g2 = start + my2;
        int4 tn[8];
        if (g2 < end) {
            const int4* xp = (const int4*)(X + (long long)(g2 << 5) * 32);
            #pragma unroll
            for (int h = 0; h < 8; h++) tn[h] = xp[h * 32 + lane];
        }

        int base = g << 5;

        // init: p[0..7] = U row (8 f32x2 pairs)
        unsigned long long p[8];
        {
            const ulonglong2* Up = (const ulonglong2*)(sU + (mask & 1023u) * UW_STRIDE);
            ulonglong2 a0 = Up[0], a1 = Up[1], a2 = Up[2], a3 = Up[3];
            p[0] = a0.x; p[1] = a0.y; p[2] = a1.x; p[3] = a1.y;
            p[4] = a2.x; p[5] = a2.y; p[6] = a3.x; p[7] = a3.y;
        }

        // two fp16 pair-product stages
        #pragma unroll
        for (int st = 0; st < 2; st++) {
            unsigned idx = (mask >> (10 + 6 * st)) & 63u;
            const uint4* M = (const uint4*)(sP + (st * 64 + idx) * P_STRIDE_H);
            unsigned long long acc[8];
            #pragma unroll
            for (int i = 0; i < 8; i++) {        // rows 2i and 2i+1
                float lo, hi;
                unpack2(p[i], lo, hi);
                unsigned long long bl = pack2(lo, lo);
                unsigned long long bh = pack2(hi, hi);
                uint4 ra = M[4 * i + 0];         // row 2i   cols 0..7
                uint4 rb = M[4 * i + 1];         // row 2i   cols 8..15
                uint4 rc = M[4 * i + 2];         // row 2i+1 cols 0..7
                uint4 rd = M[4 * i + 3];         // row 2i+1 cols 8..15
                if (i == 0) {
                    acc[0] = fmul2(bl, h2f2(ra.x)); acc[1] = fmul2(bl, h2f2(ra.y));
                    acc[2] = fmul2(bl, h2f2(ra.z)); acc[3] = fmul2(bl, h2f2(ra.w));
                    acc[4] = fmul2(bl, h2f2(rb.x)); acc[5] = fmul2(bl, h2f2(rb.y));
                    acc[6] = fmul2(bl, h2f2(rb.z)); acc[7] = fmul2(bl, h2f2(rb.w));
                } else {
                    acc[0] = ffma2(bl, h2f2(ra.x), acc[0]); acc[1] = ffma2(bl, h2f2(ra.y), acc[1]);
                    acc[2] = ffma2(bl, h2f2(ra.z), acc[2]); acc[3] = ffma2(bl, h2f2(ra.w), acc[3]);
                    acc[4] = ffma2(bl, h2f2(rb.x), acc[4]); acc[5] = ffma2(bl, h2f2(rb.y), acc[5]);
                    acc[6] = ffma2(bl, h2f2(rb.z), acc[6]); acc[7] = ffma2(bl, h2f2(rb.w), acc[7]);
                }
                acc[0] = ffma2(bh, h2f2(rc.x), acc[0]); acc[1] = ffma2(bh, h2f2(rc.y), acc[1]);
                acc[2] = ffma2(bh, h2f2(rc.z), acc[2]); acc[3] = ffma2(bh, h2f2(rc.w), acc[3]);
                acc[4] = ffma2(bh, h2f2(rd.x), acc[4]); acc[5] = ffma2(bh, h2f2(rd.y), acc[5]);
                acc[6] = ffma2(bh, h2f2(rd.z), acc[6]); acc[7] = ffma2(bh, h2f2(rd.w), acc[7]);
            }
            #pragma unroll
            for (int i = 0; i < 8; i++) p[i] = acc[i];
        }

        // final: dot(p, W[bits 22..31]) with two packed chains
        {
            const ulonglong2* Wp = (const ulonglong2*)(sW + (mask >> 22) * UW_STRIDE);
            ulonglong2 w0 = Wp[0], w1 = Wp[1], w2 = Wp[2], w3 = Wp[3];
            unsigned long long cA = fmul2(p[0], w0.x);
            unsigned long long cB = fmul2(p[1], w0.y);
            cA = ffma2(p[2], w1.x, cA);  cB = ffma2(p[3], w1.y, cB);
            cA = ffma2(p[4], w2.x, cA);  cB = ffma2(p[5], w2.y, cB);
            cA = ffma2(p[6], w3.x, cA);  cB = ffma2(p[7], w3.y, cB);
            cA = fadd2(cA, cB);
            float lo, hi;
            unpack2(cA, lo, hi);
            out[base + lane] = lo + hi;
        }

        // ---- pipeline epilogue: fold next group's loads into masks ----
        if (g2 < end) mask = ortree_masks(tn, lane);
        g = g2;
    }
}

// ---------------------------------------------------------------------------
extern "C" void kernel_launch(void* const* d_in, const int* in_sizes, int n_in,
                              void* d_out, int out_size) {
    const int*   X  = (const int*)d_in[0];
    const float* cf = (const float*)d_in[1];
    const float* cm = (const float*)d_in[2];
    const float* cl = (const float*)d_in[3];
    float* out = (float*)d_out;

    int B = in_sizes[0] / 32;       // 262144

    prep<<<256, 256>>>(cf, cm, cl);

    int nsm = 148;
    cudaDeviceGetAttribute(&nsm, cudaDevAttrMultiProcessorCount, 0);

    cudaFuncSetAttribute(tt_main, cudaFuncAttributeMaxDynamicSharedMemorySize, SMEM_BYTES);
    tt_main<<<nsm, NTHR, SMEM_BYTES>>>(X, out, B);
}